// round 9
// baseline (speedup 1.0000x reference)
#include <cuda_runtime.h>
#include <cstdint>

#define DEPTH 10
#define WIDTH 512
#define LVL_ELEMS (DEPTH * WIDTH)   // 5120 floats per (b,t)
#define TPB 128                     // 4 columns per thread
#define STAGES 2
#define BLKS_PER_SM 5

__device__ __forceinline__ float sigmoidf(float v) {
    // sigmoid(x) = 0.5 * tanh(x/2) + 0.5 — single MUFU (HW tanh) + MUL + FMA
    float t;
    asm("tanh.approx.f32 %0, %1;" : "=f"(t) : "f"(v * 0.5f));
    return fmaf(t, 0.5f, 0.5f);
}

template <int W>
__device__ __forceinline__ float allred(float v) {
    #pragma unroll
    for (int ofs = 1; ofs < W; ofs <<= 1)
        v += __shfl_xor_sync(0xffffffffu, v, ofs);
    return v;
}

// Issue 10 cp.async.cg (16B each) for this thread's 4 columns at every level.
// L1-bypassing, register-free prefetch into smem stage buffer.
__device__ __forceinline__ void issue_stage(const float* __restrict__ x, int bt,
                                            int tid, uint32_t sdst) {
    const float* g = x + (size_t)bt * LVL_ELEMS + 4 * tid;
    #pragma unroll
    for (int j = 0; j < DEPTH; ++j) {
        asm volatile("cp.async.cg.shared.global [%0], [%1], 16;\n"
                     :: "r"(sdst + j * (WIDTH * 4)), "l"(g + j * WIDTH)
                     : "memory");
    }
}

__global__ void __launch_bounds__(TPB, BLKS_PER_SM)
NCT_82162724372482_kernel(const float* __restrict__ x, float* __restrict__ out,
                          int n_bt) {
    __shared__ float buf[STAGES][LVL_ELEMS];   // 2 x 20 KB stream buffer
    __shared__ float ws0[4], ws1[4], wsf[4];

    const int tid  = threadIdx.x;
    const int warp = tid >> 5;
    const int lane = tid & 31;
    const int nb   = gridDim.x;

    // Per-stage smem address of this thread's words (columns 4*tid..4*tid+3)
    uint32_t sbase[STAGES];
    #pragma unroll
    for (int s = 0; s < STAGES; ++s)
        sbase[s] = (uint32_t)__cvta_generic_to_shared(&buf[s][4 * tid]);

    // Prologue: fill both stages (always commit to keep group accounting uniform)
    #pragma unroll
    for (int s = 0; s < STAGES; ++s) {
        int bt = blockIdx.x + s * nb;
        if (bt < n_bt) issue_stage(x, bt, tid, sbase[s]);
        asm volatile("cp.async.commit_group;\n" ::: "memory");
    }

    int iter = 0;
    for (int bt = blockIdx.x; bt < n_bt; bt += nb, ++iter) {
        const int s = iter & (STAGES - 1);

        // Wait until the group for this stage has landed (<= STAGES-1 pending).
        asm volatile("cp.async.wait_group %0;\n" :: "n"(STAGES - 1) : "memory");

        // Consume this thread's own words: sigmoid + per-level 4-col sums.
        float sum4[DEPTH];
        float4 sg8, sg9;
        #pragma unroll
        for (int j = 0; j < DEPTH; ++j) {
            float4 v = *reinterpret_cast<const float4*>(&buf[s][j * WIDTH + 4 * tid]);
            float a = sigmoidf(v.x);
            float b = sigmoidf(v.y);
            float c = sigmoidf(v.z);
            float d = sigmoidf(v.w);
            sum4[j] = (a + b) + (c + d);
            if (j == 8) sg8 = make_float4(a, b, c, d);
            if (j == 9) sg9 = make_float4(a, b, c, d);
        }

        // Intra-warp segment means (segment at level j = 128>>j threads)
        float d1[8];
        d1[7] = sum4[7] * 0.25f;
        d1[6] = allred<2>(sum4[6])  * (1.0f / 8.0f);
        d1[5] = allred<4>(sum4[5])  * (1.0f / 16.0f);
        d1[4] = allred<8>(sum4[4])  * (1.0f / 32.0f);
        d1[3] = allred<16>(sum4[3]) * (1.0f / 64.0f);
        d1[2] = allred<32>(sum4[2]) * (1.0f / 128.0f);

        float w1 = allred<32>(sum4[1]);
        float w0 = allred<32>(sum4[0]);
        if (lane == 0) { ws1[warp] = w1; ws0[warp] = w0; }
        __syncthreads();

        // All LDS values consumed above (scoreboard-drained before the barrier):
        // safe to reissue this stage. Prefetch distance = STAGES.
        {
            int nbt = bt + STAGES * nb;
            if (nbt < n_bt) issue_stage(x, nbt, tid, sbase[s]);
            asm volatile("cp.async.commit_group;\n" ::: "memory");
        }

        d1[1] = (ws1[warp] + ws1[warp ^ 1]) * (1.0f / 256.0f);
        d1[0] = ((ws0[0] + ws0[1]) + (ws0[2] + ws0[3])) * (1.0f / 512.0f);

        // Path product for levels 0..6 — identical for all 4 leaves of this thread.
        float common = 1.0f;
        #pragma unroll
        for (int j = 0; j <= 6; ++j) {
            int bit = (tid >> (6 - j)) & 1;
            common *= bit ? d1[j] : (1.0f - d1[j]);
        }

        // Levels 7..9 in closed form over this thread's 4 leaves.
        float d8a  = (sg8.x + sg8.y) * 0.5f;
        float d8b  = (sg8.z + sg8.w) * 0.5f;
        float left  = (1.0f - d8a) * sg9.x + d8a * sg9.y;
        float right = (1.0f - d8b) * sg9.z + d8b * sg9.w;
        float tv = common * ((1.0f - d1[7]) * left + d1[7] * right);

        tv = allred<32>(tv);
        if (lane == 0) wsf[warp] = tv;
        __syncthreads();
        if (tid == 0) out[bt] = (wsf[0] + wsf[1]) + (wsf[2] + wsf[3]);
    }
}

extern "C" void kernel_launch(void* const* d_in, const int* in_sizes, int n_in,
                              void* d_out, int out_size) {
    const float* x = (const float*)d_in[0];
    float* out = (float*)d_out;
    const int n_bt = in_sizes[0] / LVL_ELEMS;   // BATCH * NUM_TREES = 16384

    int sms = 0;
    if (cudaDeviceGetAttribute(&sms, cudaDevAttrMultiProcessorCount, 0) != cudaSuccess
        || sms <= 0)
        sms = 152;                               // GB300 fallback
    int blocks = sms * BLKS_PER_SM;
    if (blocks > n_bt) blocks = n_bt;

    NCT_82162724372482_kernel<<<blocks, TPB>>>(x, out, n_bt);
}

// round 10
// speedup vs baseline: 1.0811x; 1.0811x over previous
#include <cuda_runtime.h>

#define DEPTH 10
#define WIDTH 512
#define LVL_ELEMS (DEPTH * WIDTH)   // 5120 floats per (b,t)
#define TPB 128                     // 4 columns per thread

__device__ __forceinline__ float sigmoidf(float v) {
    // sigmoid(x) = 0.5 * tanh(x/2) + 0.5 — single MUFU (HW tanh) + MUL + FMA
    float t;
    asm("tanh.approx.f32 %0, %1;" : "=f"(t) : "f"(v * 0.5f));
    return fmaf(t, 0.5f, 0.5f);
}

template <int W>
__device__ __forceinline__ float allred(float v) {
    #pragma unroll
    for (int ofs = 1; ofs < W; ofs <<= 1)
        v += __shfl_xor_sync(0xffffffffu, v, ofs);
    return v;
}

__global__ void __launch_bounds__(TPB, 10)
NCT_82162724372482_kernel(const float* __restrict__ x, float* __restrict__ out) {
    __shared__ float ws0[4], ws1[4], wsf[4];

    const int bt   = blockIdx.x;            // b*NUM_TREES + t
    const int tid  = threadIdx.x;           // column group: cols [4*tid, 4*tid+3]
    const int warp = tid >> 5;
    const int lane = tid & 31;

    const float4* __restrict__ x4 =
        reinterpret_cast<const float4*>(x) + (size_t)bt * (LVL_ELEMS / 4) + tid;

    // Front-batched loads: 10 independent LDG.128 (MLP=10)
    float4 v[DEPTH];
    #pragma unroll
    for (int j = 0; j < DEPTH; ++j) v[j] = x4[j * (WIDTH / 4)];

    // Sigmoids + per-thread (4-column) sums per level
    float sum4[DEPTH];
    float4 sg8, sg9;
    #pragma unroll
    for (int j = 0; j < DEPTH; ++j) {
        float a = sigmoidf(v[j].x);
        float b = sigmoidf(v[j].y);
        float c = sigmoidf(v[j].z);
        float d = sigmoidf(v[j].w);
        sum4[j] = (a + b) + (c + d);
        if (j == 8) sg8 = make_float4(a, b, c, d);
        if (j == 9) sg9 = make_float4(a, b, c, d);
    }

    // d1[j] = mean of level-j sigmoids over the segment containing this
    // thread's columns. Segment at level j has 512>>j columns = 128>>j threads.
    float d1[8];
    d1[7] = sum4[7] * 0.25f;                       // 1 thread
    d1[6] = allred<2>(sum4[6])  * (1.0f / 8.0f);   // 2 threads
    d1[5] = allred<4>(sum4[5])  * (1.0f / 16.0f);
    d1[4] = allred<8>(sum4[4])  * (1.0f / 32.0f);
    d1[3] = allred<16>(sum4[3]) * (1.0f / 64.0f);
    d1[2] = allred<32>(sum4[2]) * (1.0f / 128.0f); // full warp

    // Levels 0 and 1 span multiple warps: warp-sum then tiny smem combine
    float w1 = allred<32>(sum4[1]);
    float w0 = allred<32>(sum4[0]);
    if (lane == 0) { ws1[warp] = w1; ws0[warp] = w0; }
    __syncthreads();
    d1[1] = (ws1[warp] + ws1[warp ^ 1]) * (1.0f / 256.0f);
    d1[0] = ((ws0[0] + ws0[1]) + (ws0[2] + ws0[3])) * (1.0f / 512.0f);

    // Path product for levels 0..6 — identical for all 4 leaves of this thread.
    // Leaf s = 4*tid + k; bit at level j is (tid >> (6-j)) & 1 for j<=6.
    float common = 1.0f;
    #pragma unroll
    for (int j = 0; j <= 6; ++j) {
        int bit = (tid >> (6 - j)) & 1;
        common *= bit ? d1[j] : (1.0f - d1[j]);
    }

    // Close the last 3 levels in closed form over the 4 leaves:
    //   level 8 means: d8a = mean(sg8.x, sg8.y) [leaves k=0,1], d8b [k=2,3]
    //   level 9 weight: sig9 per leaf
    float d8a  = (sg8.x + sg8.y) * 0.5f;
    float d8b  = (sg8.z + sg8.w) * 0.5f;
    float left  = (1.0f - d8a) * sg9.x + d8a * sg9.y;  // k=0,1 (level-7 bit = 0)
    float right = (1.0f - d8b) * sg9.z + d8b * sg9.w;  // k=2,3 (level-7 bit = 1)
    float tv = common * ((1.0f - d1[7]) * left + d1[7] * right);

    // Block reduction -> one scalar per (b,t)
    tv = allred<32>(tv);
    if (lane == 0) wsf[warp] = tv;
    __syncthreads();
    if (tid == 0) out[bt] = (wsf[0] + wsf[1]) + (wsf[2] + wsf[3]);
}

extern "C" void kernel_launch(void* const* d_in, const int* in_sizes, int n_in,
                              void* d_out, int out_size) {
    const float* x = (const float*)d_in[0];
    float* out = (float*)d_out;
    const int n_bt = in_sizes[0] / LVL_ELEMS;   // BATCH * NUM_TREES = 16384
    NCT_82162724372482_kernel<<<n_bt, TPB>>>(x, out);
}

// round 11
// speedup vs baseline: 1.0886x; 1.0069x over previous
#include <cuda_runtime.h>

#define DEPTH 10
#define WIDTH 512
#define LVL_ELEMS (DEPTH * WIDTH)   // 5120 floats per (b,t)
#define TPB 128                     // 4 columns per thread

__device__ __forceinline__ float sigmoidf(float v) {
    // sigmoid(x) = 0.5 * tanh(x/2) + 0.5 — single MUFU (HW tanh) + MUL + FMA
    float t;
    asm("tanh.approx.f32 %0, %1;" : "=f"(t) : "f"(v * 0.5f));
    return fmaf(t, 0.5f, 0.5f);
}

template <int W>
__device__ __forceinline__ float allred(float v) {
    #pragma unroll
    for (int ofs = 1; ofs < W; ofs <<= 1)
        v += __shfl_xor_sync(0xffffffffu, v, ofs);
    return v;
}

__global__ void __launch_bounds__(TPB, 10)
NCT_82162724372482_kernel(const float* __restrict__ x, float* __restrict__ out) {
    __shared__ float ws0[4], ws1[4], wsf[4];

    const int bt   = blockIdx.x;            // b*NUM_TREES + t
    const int tid  = threadIdx.x;           // column group: cols [4*tid, 4*tid+3]
    const int warp = tid >> 5;
    const int lane = tid & 31;

    const float4* __restrict__ x4 =
        reinterpret_cast<const float4*>(x) + (size_t)bt * (LVL_ELEMS / 4) + tid;

    // Front-batched loads: 10 independent LDG.128, evict-first (stream, no reuse)
    float4 v[DEPTH];
    #pragma unroll
    for (int j = 0; j < DEPTH; ++j) v[j] = __ldcs(&x4[j * (WIDTH / 4)]);

    // Sigmoids + per-thread (4-column) sums per level
    float sum4[DEPTH];
    float4 sg8, sg9;
    #pragma unroll
    for (int j = 0; j < DEPTH; ++j) {
        float a = sigmoidf(v[j].x);
        float b = sigmoidf(v[j].y);
        float c = sigmoidf(v[j].z);
        float d = sigmoidf(v[j].w);
        sum4[j] = (a + b) + (c + d);
        if (j == 8) sg8 = make_float4(a, b, c, d);
        if (j == 9) sg9 = make_float4(a, b, c, d);
    }

    // d1[j] = mean of level-j sigmoids over the segment containing this
    // thread's columns. Segment at level j has 512>>j columns = 128>>j threads.
    float d1[8];
    d1[7] = sum4[7] * 0.25f;                       // 1 thread
    d1[6] = allred<2>(sum4[6])  * (1.0f / 8.0f);   // 2 threads
    d1[5] = allred<4>(sum4[5])  * (1.0f / 16.0f);
    d1[4] = allred<8>(sum4[4])  * (1.0f / 32.0f);
    d1[3] = allred<16>(sum4[3]) * (1.0f / 64.0f);
    d1[2] = allred<32>(sum4[2]) * (1.0f / 128.0f); // full warp

    // Levels 0 and 1 span multiple warps: warp-sum then tiny smem combine
    float w1 = allred<32>(sum4[1]);
    float w0 = allred<32>(sum4[0]);
    if (lane == 0) { ws1[warp] = w1; ws0[warp] = w0; }
    __syncthreads();
    d1[1] = (ws1[warp] + ws1[warp ^ 1]) * (1.0f / 256.0f);
    d1[0] = ((ws0[0] + ws0[1]) + (ws0[2] + ws0[3])) * (1.0f / 512.0f);

    // Path product for levels 0..6 — identical for all 4 leaves of this thread.
    // Leaf s = 4*tid + k; bit at level j is (tid >> (6-j)) & 1 for j<=6.
    float common = 1.0f;
    #pragma unroll
    for (int j = 0; j <= 6; ++j) {
        int bit = (tid >> (6 - j)) & 1;
        common *= bit ? d1[j] : (1.0f - d1[j]);
    }

    // Close the last 3 levels in closed form over the 4 leaves:
    //   level 8 means: d8a = mean(sg8.x, sg8.y) [leaves k=0,1], d8b [k=2,3]
    //   level 9 weight: sig9 per leaf
    float d8a  = (sg8.x + sg8.y) * 0.5f;
    float d8b  = (sg8.z + sg8.w) * 0.5f;
    float left  = (1.0f - d8a) * sg9.x + d8a * sg9.y;  // k=0,1 (level-7 bit = 0)
    float right = (1.0f - d8b) * sg9.z + d8b * sg9.w;  // k=2,3 (level-7 bit = 1)
    float tv = common * ((1.0f - d1[7]) * left + d1[7] * right);

    // Block reduction -> one scalar per (b,t)
    tv = allred<32>(tv);
    if (lane == 0) wsf[warp] = tv;
    __syncthreads();
    if (tid == 0) out[bt] = (wsf[0] + wsf[1]) + (wsf[2] + wsf[3]);
}

extern "C" void kernel_launch(void* const* d_in, const int* in_sizes, int n_in,
                              void* d_out, int out_size) {
    const float* x = (const float*)d_in[0];
    float* out = (float*)d_out;
    const int n_bt = in_sizes[0] / LVL_ELEMS;   // BATCH * NUM_TREES = 16384
    NCT_82162724372482_kernel<<<n_bt, TPB>>>(x, out);
}

// round 12
// speedup vs baseline: 1.1167x; 1.0258x over previous
#include <cuda_runtime.h>

#define DEPTH 10
#define WIDTH 512
#define LVL_ELEMS (DEPTH * WIDTH)   // 5120 floats per (b,t)
#define TPB 128                     // 4 columns per thread

__device__ __forceinline__ float sigmoidf(float v) {
    // sigmoid(x) = 0.5 * tanh(x/2) + 0.5 — single MUFU (HW tanh) + MUL + FMA
    float t;
    asm("tanh.approx.f32 %0, %1;" : "=f"(t) : "f"(v * 0.5f));
    return fmaf(t, 0.5f, 0.5f);
}

// Streaming LDG.128 with evict-first policy + 256B L2 prefetch hint.
__device__ __forceinline__ float4 ldg_stream(const float4* p) {
    float4 v;
    asm("ld.global.cs.L2::256B.v4.f32 {%0,%1,%2,%3}, [%4];"
        : "=f"(v.x), "=f"(v.y), "=f"(v.z), "=f"(v.w) : "l"(p));
    return v;
}

template <int W>
__device__ __forceinline__ float allred(float v) {
    #pragma unroll
    for (int ofs = 1; ofs < W; ofs <<= 1)
        v += __shfl_xor_sync(0xffffffffu, v, ofs);
    return v;
}

__global__ void __launch_bounds__(TPB, 10)
NCT_82162724372482_kernel(const float* __restrict__ x, float* __restrict__ out) {
    __shared__ float ws0[4], ws1[4], wsf[4];

    const int bt   = blockIdx.x;            // b*NUM_TREES + t
    const int tid  = threadIdx.x;           // column group: cols [4*tid, 4*tid+3]
    const int warp = tid >> 5;
    const int lane = tid & 31;

    const float4* __restrict__ x4 =
        reinterpret_cast<const float4*>(x) + (size_t)bt * (LVL_ELEMS / 4) + tid;

    // Front-batched loads: 10 independent LDG.128 (MLP=10)
    float4 v[DEPTH];
    #pragma unroll
    for (int j = 0; j < DEPTH; ++j) v[j] = ldg_stream(&x4[j * (WIDTH / 4)]);

    // Sigmoids + per-thread (4-column) sums per level
    float sum4[DEPTH];
    float4 sg8, sg9;
    #pragma unroll
    for (int j = 0; j < DEPTH; ++j) {
        float a = sigmoidf(v[j].x);
        float b = sigmoidf(v[j].y);
        float c = sigmoidf(v[j].z);
        float d = sigmoidf(v[j].w);
        sum4[j] = (a + b) + (c + d);
        if (j == 8) sg8 = make_float4(a, b, c, d);
        if (j == 9) sg9 = make_float4(a, b, c, d);
    }

    // d1[j] = mean of level-j sigmoids over the segment containing this
    // thread's columns. Segment at level j has 512>>j columns = 128>>j threads.
    float d1[8];
    d1[7] = sum4[7] * 0.25f;                       // 1 thread
    d1[6] = allred<2>(sum4[6])  * (1.0f / 8.0f);   // 2 threads
    d1[5] = allred<4>(sum4[5])  * (1.0f / 16.0f);
    d1[4] = allred<8>(sum4[4])  * (1.0f / 32.0f);
    d1[3] = allred<16>(sum4[3]) * (1.0f / 64.0f);
    d1[2] = allred<32>(sum4[2]) * (1.0f / 128.0f); // full warp

    // Levels 0 and 1 span multiple warps: warp-sum then tiny smem combine
    float w1 = allred<32>(sum4[1]);
    float w0 = allred<32>(sum4[0]);
    if (lane == 0) { ws1[warp] = w1; ws0[warp] = w0; }
    __syncthreads();
    d1[1] = (ws1[warp] + ws1[warp ^ 1]) * (1.0f / 256.0f);
    d1[0] = ((ws0[0] + ws0[1]) + (ws0[2] + ws0[3])) * (1.0f / 512.0f);

    // Path product for levels 0..6 — identical for all 4 leaves of this thread.
    // Leaf s = 4*tid + k; bit at level j is (tid >> (6-j)) & 1 for j<=6.
    float common = 1.0f;
    #pragma unroll
    for (int j = 0; j <= 6; ++j) {
        int bit = (tid >> (6 - j)) & 1;
        common *= bit ? d1[j] : (1.0f - d1[j]);
    }

    // Close the last 3 levels in closed form over the 4 leaves:
    //   level 8 means: d8a = mean(sg8.x, sg8.y) [leaves k=0,1], d8b [k=2,3]
    //   level 9 weight: sig9 per leaf
    float d8a  = (sg8.x + sg8.y) * 0.5f;
    float d8b  = (sg8.z + sg8.w) * 0.5f;
    float left  = (1.0f - d8a) * sg9.x + d8a * sg9.y;  // k=0,1 (level-7 bit = 0)
    float right = (1.0f - d8b) * sg9.z + d8b * sg9.w;  // k=2,3 (level-7 bit = 1)
    float tv = common * ((1.0f - d1[7]) * left + d1[7] * right);

    // Block reduction -> one scalar per (b,t)
    tv = allred<32>(tv);
    if (lane == 0) wsf[warp] = tv;
    __syncthreads();
    if (tid == 0) out[bt] = (wsf[0] + wsf[1]) + (wsf[2] + wsf[3]);
}

extern "C" void kernel_launch(void* const* d_in, const int* in_sizes, int n_in,
                              void* d_out, int out_size) {
    const float* x = (const float*)d_in[0];
    float* out = (float*)d_out;
    const int n_bt = in_sizes[0] / LVL_ELEMS;   // BATCH * NUM_TREES = 16384
    NCT_82162724372482_kernel<<<n_bt, TPB>>>(x, out);
}